// round 1
// baseline (speedup 1.0000x reference)
#include <cuda_runtime.h>
#include <math.h>

#define B 4
#define N 20000
#define M 1024
#define PL 50

// Scratch (allocation-free rule: __device__ globals)
__device__ int    g_p2n[B * N];
__device__ float  g_dist[B * N];
__device__ float  g_ptsT[B * N * 3];
__device__ int    g_count[B * M];
__device__ int    g_off[B * M];
__device__ int    g_cur[B * M];
__device__ int    g_lidx[B * N];
__device__ float  g_ld[B * N];
__device__ double g_accA;
__device__ double g_accW;

__global__ void k_init() {
    int i = blockIdx.x * blockDim.x + threadIdx.x;
    if (i < B * M) g_count[i] = 0;
    if (i == 0) { g_accA = 0.0; g_accW = 0.0; }
}

#define K1_THREADS 256
#define PPT 4   // points per thread

// Per-point nearest keypoint (argmin over M), transformed points, per-keypoint counts.
__global__ void k_assign(const float* __restrict__ pts,
                         const float* __restrict__ kp,
                         const float* __restrict__ pose) {
    __shared__ float4 skp[M];
    __shared__ float sR[9];
    __shared__ float st[3];

    const int b = blockIdx.y;
    const float* kpb = kp + (size_t)b * M * 3;
    for (int m = threadIdx.x; m < M; m += blockDim.x) {
        float kx = kpb[m * 3 + 0];
        float ky = kpb[m * 3 + 1];
        float kz = kpb[m * 3 + 2];
        skp[m] = make_float4(kx, ky, kz, kx * kx + ky * ky + kz * kz);
    }
    if (threadIdx.x < 12) {
        int r = threadIdx.x >> 2, c = threadIdx.x & 3;
        float v = pose[b * 16 + r * 4 + c];
        if (c < 3) sR[r * 3 + c] = v; else st[r] = v;
    }
    __syncthreads();

    const int base = blockIdx.x * (K1_THREADS * PPT);
    float px[PPT], py[PPT], pz[PPT], pp[PPT], bestv[PPT];
    int bestm[PPT];

#pragma unroll
    for (int j = 0; j < PPT; j++) {
        int p = base + j * K1_THREADS + threadIdx.x;
        float x = 0.f, y = 0.f, z = 0.f;
        if (p < N) {
            const float* q = pts + ((size_t)b * N + p) * 3;
            x = q[0]; y = q[1]; z = q[2];
        }
        px[j] = x; py[j] = y; pz[j] = z;
        pp[j] = x * x + y * y + z * z;
        bestv[j] = INFINITY;
        bestm[j] = 0;
    }

    for (int m = 0; m < M; m++) {
        float4 k = skp[m];
#pragma unroll
        for (int j = 0; j < PPT; j++) {
            float dot = k.x * px[j] + k.y * py[j] + k.z * pz[j];
            float s = k.w + pp[j] - 2.0f * dot;
            if (s < bestv[j]) { bestv[j] = s; bestm[j] = m; }  // strict < : first-min like jnp.argmin
        }
    }

#pragma unroll
    for (int j = 0; j < PPT; j++) {
        int p = base + j * K1_THREADS + threadIdx.x;
        if (p >= N) continue;
        int gi = b * N + p;
        g_p2n[gi] = bestm[j];
        g_dist[gi] = bestv[j];
        float tx = sR[0] * px[j] + sR[1] * py[j] + sR[2] * pz[j] + st[0];
        float ty = sR[3] * px[j] + sR[4] * py[j] + sR[5] * pz[j] + st[1];
        float tz = sR[6] * px[j] + sR[7] * py[j] + sR[8] * pz[j] + st[2];
        g_ptsT[gi * 3 + 0] = tx;
        g_ptsT[gi * 3 + 1] = ty;
        g_ptsT[gi * 3 + 2] = tz;
        atomicAdd(&g_count[b * M + bestm[j]], 1);
    }
}

// Exclusive scan of counts per batch -> CSR offsets (one block of M threads per batch).
__global__ void k_scan() {
    __shared__ int s[M];
    int b = blockIdx.x;
    int t = threadIdx.x;
    int v = g_count[b * M + t];
    s[t] = v;
    __syncthreads();
    for (int off = 1; off < M; off <<= 1) {
        int add = (t >= off) ? s[t - off] : 0;
        __syncthreads();
        s[t] += add;
        __syncthreads();
    }
    int excl = s[t] - v;
    g_off[b * M + t] = b * N + excl;
    g_cur[b * M + t] = b * N + excl;
}

__global__ void k_scatter() {
    int i = blockIdx.x * blockDim.x + threadIdx.x;
    if (i >= B * N) return;
    int b = i / N;
    int p = i - b * N;
    int m = g_p2n[i];
    int pos = atomicAdd(&g_cur[b * M + m], 1);
    g_lidx[pos] = p;
    g_ld[pos] = g_dist[i];
}

// Per (b, m): select min(count,50) nearest assigned points (lex (dist, idx) — matches
// lax.top_k stability), pad with smallest indices n where p2n[n] != m (FAR tie-break),
// sum transformed points, accumulate weighted L1.
__global__ void k_select(const float* __restrict__ kpw,
                         const float* __restrict__ ow) {
    int i = blockIdx.x * blockDim.x + threadIdx.x;
    if (i >= B * M) return;
    int b = i / M;
    int m = i - b * M;

    int c = g_count[i];
    int start = g_off[i];
    float sx = 0.f, sy = 0.f, sz = 0.f;
    int fill;

    if (c <= PL) {
        for (int j = 0; j < c; j++) {
            int p = g_lidx[start + j];
            const float* q = &g_ptsT[((size_t)b * N + p) * 3];
            sx += q[0]; sy += q[1]; sz += q[2];
        }
        fill = PL - c;
    } else {
        float sd[PL];
        int   si[PL];
        int size = 0;
        for (int j = 0; j < c; j++) {
            float d = g_ld[start + j];
            int   p = g_lidx[start + j];
            if (size < PL) {
                int pos = size++;
                while (pos > 0 && (sd[pos - 1] > d ||
                                   (sd[pos - 1] == d && si[pos - 1] > p))) {
                    sd[pos] = sd[pos - 1]; si[pos] = si[pos - 1]; pos--;
                }
                sd[pos] = d; si[pos] = p;
            } else if (d < sd[PL - 1] || (d == sd[PL - 1] && p < si[PL - 1])) {
                int pos = PL - 1;
                while (pos > 0 && (sd[pos - 1] > d ||
                                   (sd[pos - 1] == d && si[pos - 1] > p))) {
                    sd[pos] = sd[pos - 1]; si[pos] = si[pos - 1]; pos--;
                }
                sd[pos] = d; si[pos] = p;
            }
        }
        for (int j = 0; j < PL; j++) {
            const float* q = &g_ptsT[((size_t)b * N + si[j]) * 3];
            sx += q[0]; sy += q[1]; sz += q[2];
        }
        fill = 0;
    }

    // Fillers: smallest point indices not assigned to m (FAR entries, stable tie-break).
    const int* p2nb = g_p2n + (size_t)b * N;
    int n = 0;
    while (fill > 0) {
        if (p2nb[n] != m) {
            const float* q = &g_ptsT[((size_t)b * N + n) * 3];
            sx += q[0]; sy += q[1]; sz += q[2];
            fill--;
        }
        n++;
    }

    float ex = sx / (float)PL - kpw[i * 3 + 0];
    float ey = sy / (float)PL - kpw[i * 3 + 1];
    float ez = sz / (float)PL - kpw[i * 3 + 2];
    float l1 = fabsf(ex) + fabsf(ey) + fabsf(ez);
    float w = ow[i];
    atomicAdd(&g_accA, (double)(w * l1));
    atomicAdd(&g_accW, (double)w);
}

__global__ void k_final(float* __restrict__ out) {
    double sw = g_accW;
    if (sw < 1e-6) sw = 1e-6;
    out[0] = (float)(g_accA / sw);
}

extern "C" void kernel_launch(void* const* d_in, const int* in_sizes, int n_in,
                              void* d_out, int out_size) {
    const float* pts  = (const float*)d_in[0];  // (B, N, 3)
    const float* kp   = (const float*)d_in[1];  // (B, M, 3)
    const float* kpw  = (const float*)d_in[2];  // (B, M, 3)
    const float* pose = (const float*)d_in[3];  // (B, 4, 4)
    const float* ow   = (const float*)d_in[4];  // (B, M)
    float* out = (float*)d_out;

    k_init<<<(B * M + 255) / 256, 256>>>();

    dim3 g1((N + K1_THREADS * PPT - 1) / (K1_THREADS * PPT), B);
    k_assign<<<g1, K1_THREADS>>>(pts, kp, pose);

    k_scan<<<B, M>>>();
    k_scatter<<<(B * N + 255) / 256, 256>>>();
    k_select<<<(B * M + 255) / 256, 256>>>(kpw, ow);
    k_final<<<1, 1>>>(out);
}

// round 2
// speedup vs baseline: 1.4759x; 1.4759x over previous
#include <cuda_runtime.h>
#include <math.h>

#define B 4
#define N 20000
#define M 1024
#define PL 50

// Scratch (allocation-free rule: __device__ globals)
__device__ int    g_p2n[B * N];
__device__ float  g_dist[B * N];
__device__ float  g_ptsT[B * N * 3];
__device__ int    g_count[B * M];
__device__ int    g_off[B * M];
__device__ int    g_cur[B * M];
__device__ int    g_lidx[B * N];
__device__ float  g_ld[B * N];
__device__ double g_accA;
__device__ double g_accW;

__global__ void k_init() {
    int i = blockIdx.x * blockDim.x + threadIdx.x;
    if (i < B * M) g_count[i] = 0;
    if (i == 0) { g_accA = 0.0; g_accW = 0.0; }
}

// ---------------- k_assign: per-point argmin over M keypoints ----------------
#define K1_THREADS 128
#define PPT 2
#define PTS_PER_BLK (K1_THREADS * PPT)   // 256
#define K1_BLKS ((N + PTS_PER_BLK - 1) / PTS_PER_BLK)  // 79

__global__ __launch_bounds__(K1_THREADS) void k_assign(
        const float* __restrict__ pts,
        const float* __restrict__ kp,
        const float* __restrict__ pose) {
    __shared__ float4 skp[M];   // (x, y, z, 0.5*|k|^2)
    __shared__ float sR[9];
    __shared__ float st[3];

    const int b = blockIdx.y;
    const float* kpb = kp + (size_t)b * M * 3;
    for (int m = threadIdx.x; m < M; m += K1_THREADS) {
        float kx = kpb[m * 3 + 0];
        float ky = kpb[m * 3 + 1];
        float kz = kpb[m * 3 + 2];
        skp[m] = make_float4(kx, ky, kz, 0.5f * (kx * kx + ky * ky + kz * kz));
    }
    if (threadIdx.x < 12) {
        int r = threadIdx.x >> 2, c = threadIdx.x & 3;
        float v = pose[b * 16 + r * 4 + c];
        if (c < 3) sR[r * 3 + c] = v; else st[r] = v;
    }
    __syncthreads();

    const int base = blockIdx.x * PTS_PER_BLK;
    float px[PPT], py[PPT], pz[PPT], nx[PPT], ny[PPT], nz[PPT], bestv[PPT];
    int bestm[PPT];

#pragma unroll
    for (int j = 0; j < PPT; j++) {
        int p = base + j * K1_THREADS + threadIdx.x;
        float x = 0.f, y = 0.f, z = 0.f;
        if (p < N) {
            const float* q = pts + ((size_t)b * N + p) * 3;
            x = q[0]; y = q[1]; z = q[2];
        }
        px[j] = x; py[j] = y; pz[j] = z;
        nx[j] = -x; ny[j] = -y; nz[j] = -z;
        bestv[j] = INFINITY;
        bestm[j] = 0;
    }

    for (int m = 0; m < M; m++) {
        float4 k = skp[m];
#pragma unroll
        for (int j = 0; j < PPT; j++) {
            // v = 0.5|k|^2 - k.p  (monotone in true sq-dist for fixed point)
            float v = fmaf(k.x, nx[j], fmaf(k.y, ny[j], fmaf(k.z, nz[j], k.w)));
            bool lt = v < bestv[j];                 // strict <: first-min like jnp.argmin
            bestv[j] = lt ? v : bestv[j];
            bestm[j] = lt ? m : bestm[j];
        }
    }

#pragma unroll
    for (int j = 0; j < PPT; j++) {
        int p = base + j * K1_THREADS + threadIdx.x;
        if (p >= N) continue;
        int gi = b * N + p;
        float pp = px[j] * px[j] + py[j] * py[j] + pz[j] * pz[j];
        g_p2n[gi] = bestm[j];
        g_dist[gi] = fmaf(2.0f, bestv[j], pp);      // true squared distance
        float tx = sR[0] * px[j] + sR[1] * py[j] + sR[2] * pz[j] + st[0];
        float ty = sR[3] * px[j] + sR[4] * py[j] + sR[5] * pz[j] + st[1];
        float tz = sR[6] * px[j] + sR[7] * py[j] + sR[8] * pz[j] + st[2];
        g_ptsT[gi * 3 + 0] = tx;
        g_ptsT[gi * 3 + 1] = ty;
        g_ptsT[gi * 3 + 2] = tz;
        atomicAdd(&g_count[b * M + bestm[j]], 1);
    }
}

// ---------------- k_scan: exclusive scan of counts per batch ----------------
__global__ void k_scan() {
    __shared__ int s[M];
    int b = blockIdx.x;
    int t = threadIdx.x;
    int v = g_count[b * M + t];
    s[t] = v;
    __syncthreads();
    for (int off = 1; off < M; off <<= 1) {
        int add = (t >= off) ? s[t - off] : 0;
        __syncthreads();
        s[t] += add;
        __syncthreads();
    }
    int excl = s[t] - v;
    g_off[b * M + t] = b * N + excl;
    g_cur[b * M + t] = b * N + excl;
}

// ---------------- k_scatter: CSR fill, 4 independent chains/thread ----------
#define SC_PPT 4
__global__ void k_scatter() {
    int tid = blockIdx.x * blockDim.x + threadIdx.x;
    int tot = gridDim.x * blockDim.x;
    int idx[SC_PPT], mm[SC_PPT];
    float dd[SC_PPT];
#pragma unroll
    for (int k = 0; k < SC_PPT; k++) {
        int i = tid + k * tot;
        idx[k] = i;
        if (i < B * N) { mm[k] = g_p2n[i]; dd[k] = g_dist[i]; }
    }
#pragma unroll
    for (int k = 0; k < SC_PPT; k++) {
        int i = idx[k];
        if (i >= B * N) continue;
        int b = i / N;
        int p = i - b * N;
        int pos = atomicAdd(&g_cur[b * M + mm[k]], 1);
        g_lidx[pos] = p;
        g_ld[pos] = dd[k];
    }
}

// ---------------- k_select: one WARP per (b, m) -----------------------------
__global__ __launch_bounds__(256) void k_select(
        const float* __restrict__ kpw,
        const float* __restrict__ ow) {
    int wg = (blockIdx.x * blockDim.x + threadIdx.x) >> 5;   // global warp id
    int lane = threadIdx.x & 31;
    if (wg >= B * M) return;
    int b = wg / M;
    int m = wg - b * M;
    int i = wg;

    int c = g_count[i];
    int start = g_off[i];
    float sx = 0.f, sy = 0.f, sz = 0.f;
    int fill;

    if (c <= PL) {
        for (int j = lane; j < c; j += 32) {
            int p = g_lidx[start + j];
            const float* q = &g_ptsT[((size_t)b * N + p) * 3];
            sx += q[0]; sy += q[1]; sz += q[2];
        }
        fill = PL - c;
    } else {
        // Rare (count > 50): serial insertion-select on lane 0.
        // Lex key (dist, idx) matches lax.top_k stability.
        if (lane == 0) {
            float sd[PL];
            int   si[PL];
            int size = 0;
            for (int j = 0; j < c; j++) {
                float d = g_ld[start + j];
                int   p = g_lidx[start + j];
                if (size < PL) {
                    int pos = size++;
                    while (pos > 0 && (sd[pos - 1] > d ||
                                       (sd[pos - 1] == d && si[pos - 1] > p))) {
                        sd[pos] = sd[pos - 1]; si[pos] = si[pos - 1]; pos--;
                    }
                    sd[pos] = d; si[pos] = p;
                } else if (d < sd[PL - 1] || (d == sd[PL - 1] && p < si[PL - 1])) {
                    int pos = PL - 1;
                    while (pos > 0 && (sd[pos - 1] > d ||
                                       (sd[pos - 1] == d && si[pos - 1] > p))) {
                        sd[pos] = sd[pos - 1]; si[pos] = si[pos - 1]; pos--;
                    }
                    sd[pos] = d; si[pos] = p;
                }
            }
            for (int j = 0; j < PL; j++) {
                const float* q = &g_ptsT[((size_t)b * N + si[j]) * 3];
                sx += q[0]; sy += q[1]; sz += q[2];
            }
        }
        fill = 0;
    }

    // Fillers: first (50 - c) point indices with p2n != m (FAR pad, stable
    // tie-break = ascending index). Warp-cooperative ballot sweep.
    const int* p2nb = g_p2n + (size_t)b * N;
    int n0 = 0;
    while (fill > 0) {
        int n = n0 + lane;                 // n < ~132 << N always (fill<=50)
        bool ok = (p2nb[n] != m);
        unsigned msk = __ballot_sync(0xffffffffu, ok);
        int rank = __popc(msk & ((1u << lane) - 1u));
        if (ok && rank < fill) {
            const float* q = &g_ptsT[((size_t)b * N + n) * 3];
            sx += q[0]; sy += q[1]; sz += q[2];
        }
        fill -= min(fill, __popc(msk));
        n0 += 32;
    }

    // Warp reduce
#pragma unroll
    for (int off = 16; off; off >>= 1) {
        sx += __shfl_xor_sync(0xffffffffu, sx, off);
        sy += __shfl_xor_sync(0xffffffffu, sy, off);
        sz += __shfl_xor_sync(0xffffffffu, sz, off);
    }

    if (lane == 0) {
        float ex = sx * (1.0f / PL) - kpw[i * 3 + 0];
        float ey = sy * (1.0f / PL) - kpw[i * 3 + 1];
        float ez = sz * (1.0f / PL) - kpw[i * 3 + 2];
        float l1 = fabsf(ex) + fabsf(ey) + fabsf(ez);
        float w = ow[i];
        atomicAdd(&g_accA, (double)(w * l1));
        atomicAdd(&g_accW, (double)w);
    }
}

__global__ void k_final(float* __restrict__ out) {
    double sw = g_accW;
    if (sw < 1e-6) sw = 1e-6;
    out[0] = (float)(g_accA / sw);
}

extern "C" void kernel_launch(void* const* d_in, const int* in_sizes, int n_in,
                              void* d_out, int out_size) {
    const float* pts  = (const float*)d_in[0];  // (B, N, 3)
    const float* kp   = (const float*)d_in[1];  // (B, M, 3)
    const float* kpw  = (const float*)d_in[2];  // (B, M, 3)
    const float* pose = (const float*)d_in[3];  // (B, 4, 4)
    const float* ow   = (const float*)d_in[4];  // (B, M)
    float* out = (float*)d_out;

    k_init<<<(B * M + 255) / 256, 256>>>();

    dim3 g1(K1_BLKS, B);
    k_assign<<<g1, K1_THREADS>>>(pts, kp, pose);

    k_scan<<<B, M>>>();

    int sc_threads = 256;
    int sc_blocks = (B * N + sc_threads * SC_PPT - 1) / (sc_threads * SC_PPT);
    k_scatter<<<sc_blocks, sc_threads>>>();

    // one warp per (b, m): 4096 warps
    k_select<<<(B * M * 32 + 255) / 256, 256>>>(kpw, ow);

    k_final<<<1, 1>>>(out);
}

// round 4
// speedup vs baseline: 1.6331x; 1.1065x over previous
#include <cuda_runtime.h>
#include <math.h>

#define B 4
#define N 20000
#define M 1024
#define PL 50
#define L_CAP 192   // per-keypoint list capacity (~15 sigma above mean count 19.5)

// Scratch (allocation-free rule: __device__ globals)
__device__ int    g_p2n[B * N];
__device__ int    g_count[B * M];
__device__ int    g_lidx[B * M * L_CAP];
__device__ float  g_ldst[B * M * L_CAP];
__device__ double g_accA;
__device__ double g_accW;
__device__ int    g_done;

__global__ void k_init() {
    int i = blockIdx.x * blockDim.x + threadIdx.x;
    if (i < B * M) g_count[i] = 0;
    if (i == 0) { g_accA = 0.0; g_accW = 0.0; g_done = 0; }
}

// ---------------- k_assign: per-point argmin over M keypoints ----------------
#define K1_THREADS 128
#define PPT 2
#define PTS_PER_BLK (K1_THREADS * PPT)   // 256
#define K1_BLKS ((N + PTS_PER_BLK - 1) / PTS_PER_BLK)  // 79

__device__ __forceinline__ unsigned long long pack2(float lo, float hi) {
    unsigned long long d;
    asm("mov.b64 %0, {%1, %2};" : "=l"(d) : "f"(lo), "f"(hi));
    return d;
}

__global__ __launch_bounds__(K1_THREADS) void k_assign(
        const float* __restrict__ pts,
        const float* __restrict__ kp) {
    // duplicated keypoint layout for packed f32x2 math:
    // skpA[m] = {kx, kx, ky, ky},  skpB[m] = {kz, kz, kw, kw}, kw = 0.5*|k|^2
    __shared__ float4 skpA[M];
    __shared__ float4 skpB[M];

    const int b = blockIdx.y;
    const float* kpb = kp + (size_t)b * M * 3;
    for (int m = threadIdx.x; m < M; m += K1_THREADS) {
        float kx = kpb[m * 3 + 0];
        float ky = kpb[m * 3 + 1];
        float kz = kpb[m * 3 + 2];
        float kw = 0.5f * (kx * kx + ky * ky + kz * kz);
        skpA[m] = make_float4(kx, kx, ky, ky);
        skpB[m] = make_float4(kz, kz, kw, kw);
    }
    __syncthreads();

    const int base = blockIdx.x * PTS_PER_BLK;
    float px[PPT], py[PPT], pz[PPT], bestv[PPT];
    int bestm[PPT];

#pragma unroll
    for (int j = 0; j < PPT; j++) {
        int p = base + j * K1_THREADS + threadIdx.x;
        float x = 0.f, y = 0.f, z = 0.f;
        if (p < N) {
            const float* q = pts + ((size_t)b * N + p) * 3;
            x = q[0]; y = q[1]; z = q[2];
        }
        px[j] = x; py[j] = y; pz[j] = z;
        bestv[j] = INFINITY;
        bestm[j] = 0;
    }

    // packed negated coordinates (lo = point j0, hi = point j1)
    unsigned long long nx2 = pack2(-px[0], -px[1]);
    unsigned long long ny2 = pack2(-py[0], -py[1]);
    unsigned long long nz2 = pack2(-pz[0], -pz[1]);

#pragma unroll 4
    for (int m = 0; m < M; m++) {
        float4 a = skpA[m];
        float4 c = skpB[m];
        unsigned long long kx2, ky2, kz2, kw2, v2;
        asm("mov.b64 %0, {%1, %2};" : "=l"(kx2) : "f"(a.x), "f"(a.y));
        asm("mov.b64 %0, {%1, %2};" : "=l"(ky2) : "f"(a.z), "f"(a.w));
        asm("mov.b64 %0, {%1, %2};" : "=l"(kz2) : "f"(c.x), "f"(c.y));
        asm("mov.b64 %0, {%1, %2};" : "=l"(kw2) : "f"(c.z), "f"(c.w));
        // v = 0.5|k|^2 - k.p  (monotone in true sq-dist for a fixed point)
        asm("fma.rn.f32x2 %0, %1, %2, %3;" : "=l"(v2) : "l"(kz2), "l"(nz2), "l"(kw2));
        asm("fma.rn.f32x2 %0, %1, %2, %3;" : "=l"(v2) : "l"(ky2), "l"(ny2), "l"(v2));
        asm("fma.rn.f32x2 %0, %1, %2, %3;" : "=l"(v2) : "l"(kx2), "l"(nx2), "l"(v2));
        float v0, v1;
        asm("mov.b64 {%0, %1}, %2;" : "=f"(v0), "=f"(v1) : "l"(v2));
        // strict <: first-min like jnp.argmin
        bool lt0 = v0 < bestv[0];
        bestv[0] = lt0 ? v0 : bestv[0];
        bestm[0] = lt0 ? m : bestm[0];
        bool lt1 = v1 < bestv[1];
        bestv[1] = lt1 ? v1 : bestv[1];
        bestm[1] = lt1 ? m : bestm[1];
    }

#pragma unroll
    for (int j = 0; j < PPT; j++) {
        int p = base + j * K1_THREADS + threadIdx.x;
        if (p >= N) continue;
        int gi = b * N + p;
        int bm = b * M + bestm[j];
        float pp = px[j] * px[j] + py[j] * py[j] + pz[j] * pz[j];
        float dist = fmaf(2.0f, bestv[j], pp);      // true squared distance
        g_p2n[gi] = bestm[j];
        int pos = atomicAdd(&g_count[bm], 1);
        if (pos < L_CAP) {
            g_lidx[(size_t)bm * L_CAP + pos] = p;
            g_ldst[(size_t)bm * L_CAP + pos] = dist;
        }
    }
}

// ---------------- k_select: one WARP per (b, m), fused final reduce ---------
#define SEL_THREADS 512
#define SEL_WARPS (SEL_THREADS / 32)
#define SEL_BLOCKS (B * M / SEL_WARPS)   // 256

__global__ __launch_bounds__(SEL_THREADS) void k_select(
        const float* __restrict__ pts,
        const float* __restrict__ kpw,
        const float* __restrict__ pose,
        const float* __restrict__ ow,
        float* __restrict__ out) {
    __shared__ float s_a[SEL_WARPS];
    __shared__ float s_w[SEL_WARPS];

    int wg = (blockIdx.x * SEL_THREADS + threadIdx.x) >> 5;   // global warp id
    int wid = threadIdx.x >> 5;
    int lane = threadIdx.x & 31;
    int b = wg / M;
    int m = wg - b * M;
    int i = wg;

    const float* ptsb = pts + (size_t)b * N * 3;
    const int* lidx = g_lidx + (size_t)i * L_CAP;

    int c = g_count[i];
    int cc = min(c, L_CAP);
    float sx = 0.f, sy = 0.f, sz = 0.f;
    int fill;

    if (c <= PL) {
        for (int j = lane; j < cc; j += 32) {
            int p = lidx[j];
            const float* q = &ptsb[(size_t)p * 3];
            sx += q[0]; sy += q[1]; sz += q[2];
        }
        fill = PL - c;
    } else {
        // Rare (count > 50): serial insertion-select on lane 0.
        // Lex key (dist, idx) matches lax.top_k stability.
        if (lane == 0) {
            const float* ldst = g_ldst + (size_t)i * L_CAP;
            float sd[PL];
            int   si[PL];
            int size = 0;
            for (int j = 0; j < cc; j++) {
                float d = ldst[j];
                int   p = lidx[j];
                if (size < PL) {
                    int pos = size++;
                    while (pos > 0 && (sd[pos - 1] > d ||
                                       (sd[pos - 1] == d && si[pos - 1] > p))) {
                        sd[pos] = sd[pos - 1]; si[pos] = si[pos - 1]; pos--;
                    }
                    sd[pos] = d; si[pos] = p;
                } else if (d < sd[PL - 1] || (d == sd[PL - 1] && p < si[PL - 1])) {
                    int pos = PL - 1;
                    while (pos > 0 && (sd[pos - 1] > d ||
                                       (sd[pos - 1] == d && si[pos - 1] > p))) {
                        sd[pos] = sd[pos - 1]; si[pos] = si[pos - 1]; pos--;
                    }
                    sd[pos] = d; si[pos] = p;
                }
            }
            for (int j = 0; j < PL; j++) {
                const float* q = &ptsb[(size_t)si[j] * 3];
                sx += q[0]; sy += q[1]; sz += q[2];
            }
        }
        fill = 0;
    }

    // Fillers: first (50 - c) point indices with p2n != m (FAR pad, stable
    // tie-break = ascending index). Warp-cooperative ballot sweep.
    const int* p2nb = g_p2n + (size_t)b * N;
    int n0 = 0;
    while (fill > 0) {
        int n = n0 + lane;                 // n stays far below N (fill <= 50)
        bool ok = (p2nb[n] != m);
        unsigned msk = __ballot_sync(0xffffffffu, ok);
        int rank = __popc(msk & ((1u << lane) - 1u));
        if (ok && rank < fill) {
            const float* q = &ptsb[(size_t)n * 3];
            sx += q[0]; sy += q[1]; sz += q[2];
        }
        fill -= min(fill, __popc(msk));
        n0 += 32;
    }

    // Warp reduce
#pragma unroll
    for (int off = 16; off; off >>= 1) {
        sx += __shfl_xor_sync(0xffffffffu, sx, off);
        sy += __shfl_xor_sync(0xffffffffu, sy, off);
        sz += __shfl_xor_sync(0xffffffffu, sz, off);
    }

    float wa = 0.f, ww = 0.f;
    if (lane == 0) {
        // mean(R p + t) = R mean(p) + t
        const float* P = pose + b * 16;
        float mx = sx * (1.0f / PL), my = sy * (1.0f / PL), mz = sz * (1.0f / PL);
        float ex = P[0] * mx + P[1] * my + P[2]  * mz + P[3]  - kpw[i * 3 + 0];
        float ey = P[4] * mx + P[5] * my + P[6]  * mz + P[7]  - kpw[i * 3 + 1];
        float ez = P[8] * mx + P[9] * my + P[10] * mz + P[11] - kpw[i * 3 + 2];
        float w = ow[i];
        wa = w * (fabsf(ex) + fabsf(ey) + fabsf(ez));
        ww = w;
    }

    if (lane == 0) { s_a[wid] = wa; s_w[wid] = ww; }
    __syncthreads();
    if (threadIdx.x == 0) {
        float ba = 0.f, bw = 0.f;
#pragma unroll
        for (int k = 0; k < SEL_WARPS; k++) { ba += s_a[k]; bw += s_w[k]; }
        atomicAdd(&g_accA, (double)ba);
        atomicAdd(&g_accW, (double)bw);
        __threadfence();
        int t = atomicAdd(&g_done, 1);
        if (t == SEL_BLOCKS - 1) {
            double sw = g_accW;
            if (sw < 1e-6) sw = 1e-6;
            out[0] = (float)(g_accA / sw);
        }
    }
}

extern "C" void kernel_launch(void* const* d_in, const int* in_sizes, int n_in,
                              void* d_out, int out_size) {
    const float* pts  = (const float*)d_in[0];  // (B, N, 3)
    const float* kp   = (const float*)d_in[1];  // (B, M, 3)
    const float* kpw  = (const float*)d_in[2];  // (B, M, 3)
    const float* pose = (const float*)d_in[3];  // (B, 4, 4)
    const float* ow   = (const float*)d_in[4];  // (B, M)
    float* out = (float*)d_out;

    k_init<<<(B * M + 1023) / 1024, 1024>>>();

    dim3 g1(K1_BLKS, B);
    k_assign<<<g1, K1_THREADS>>>(pts, kp);

    k_select<<<SEL_BLOCKS, SEL_THREADS>>>(pts, kpw, pose, ow, out);
}

// round 5
// speedup vs baseline: 3.3995x; 2.0816x over previous
#include <cuda_runtime.h>
#include <math.h>

#define B 4
#define N 20000
#define M 1024
#define PL 50
#define L_CAP 192   // per-keypoint list capacity (>> max Voronoi occupancy)

// Scratch (allocation-free rule: __device__ globals, zero-initialized at load).
// Pipeline is self-resetting: k_select zeroes g_count / accumulators at the end
// of every launch, so no init kernel is needed.
__device__ int    g_p2n[B * N];
__device__ int    g_count[B * M];
__device__ int    g_lidx[B * M * L_CAP];
__device__ float  g_ldst[B * M * L_CAP];
__device__ double g_accA;
__device__ double g_accW;
__device__ int    g_done;

// ---------------- k_assign: per-point argmin over M keypoints ----------------
#define K1_THREADS 128
#define PPT 2
#define PTS_PER_BLK (K1_THREADS * PPT)   // 256
#define K1_BLKS ((N + PTS_PER_BLK - 1) / PTS_PER_BLK)  // 79

__device__ __forceinline__ unsigned long long pack2(float lo, float hi) {
    unsigned long long d;
    asm("mov.b64 %0, {%1, %2};" : "=l"(d) : "f"(lo), "f"(hi));
    return d;
}

__global__ __launch_bounds__(K1_THREADS) void k_assign(
        const float* __restrict__ pts,
        const float* __restrict__ kp) {
    // Pre-packed f32x2 keypoint layout: skpA[m] = {kx2, ky2}, skpB[m] = {kz2, kw2}
    // where each u64 holds the SAME value duplicated (lo/hi lanes = 2 points).
    __shared__ ulonglong2 skpA[M];
    __shared__ ulonglong2 skpB[M];

    const int b = blockIdx.y;
    const float* kpb = kp + (size_t)b * M * 3;
    for (int m = threadIdx.x; m < M; m += K1_THREADS) {
        float kx = kpb[m * 3 + 0];
        float ky = kpb[m * 3 + 1];
        float kz = kpb[m * 3 + 2];
        float kw = 0.5f * (kx * kx + ky * ky + kz * kz);
        ulonglong2 a, c;
        a.x = pack2(kx, kx); a.y = pack2(ky, ky);
        c.x = pack2(kz, kz); c.y = pack2(kw, kw);
        skpA[m] = a;
        skpB[m] = c;
    }
    __syncthreads();

    const int base = blockIdx.x * PTS_PER_BLK;
    float px[PPT], py[PPT], pz[PPT], bestv[PPT];
    int bestm[PPT];

#pragma unroll
    for (int j = 0; j < PPT; j++) {
        int p = base + j * K1_THREADS + threadIdx.x;
        float x = 0.f, y = 0.f, z = 0.f;
        if (p < N) {
            const float* q = pts + ((size_t)b * N + p) * 3;
            x = q[0]; y = q[1]; z = q[2];
        }
        px[j] = x; py[j] = y; pz[j] = z;
        bestv[j] = INFINITY;
        bestm[j] = 0;
    }

    // packed negated coordinates (lo = point j0, hi = point j1)
    unsigned long long nx2 = pack2(-px[0], -px[1]);
    unsigned long long ny2 = pack2(-py[0], -py[1]);
    unsigned long long nz2 = pack2(-pz[0], -pz[1]);

#pragma unroll 4
    for (int m = 0; m < M; m++) {
        ulonglong2 a = skpA[m];
        ulonglong2 c = skpB[m];
        unsigned long long v2;
        // v = 0.5|k|^2 - k.p  (monotone in true sq-dist for a fixed point)
        asm("fma.rn.f32x2 %0, %1, %2, %3;" : "=l"(v2) : "l"(c.x), "l"(nz2), "l"(c.y));
        asm("fma.rn.f32x2 %0, %1, %2, %3;" : "=l"(v2) : "l"(a.y), "l"(ny2), "l"(v2));
        asm("fma.rn.f32x2 %0, %1, %2, %3;" : "=l"(v2) : "l"(a.x), "l"(nx2), "l"(v2));
        float v0, v1;
        asm("mov.b64 {%0, %1}, %2;" : "=f"(v0), "=f"(v1) : "l"(v2));
        // strict <: first-min like jnp.argmin
        bool lt0 = v0 < bestv[0];
        bestv[0] = lt0 ? v0 : bestv[0];
        bestm[0] = lt0 ? m : bestm[0];
        bool lt1 = v1 < bestv[1];
        bestv[1] = lt1 ? v1 : bestv[1];
        bestm[1] = lt1 ? m : bestm[1];
    }

#pragma unroll
    for (int j = 0; j < PPT; j++) {
        int p = base + j * K1_THREADS + threadIdx.x;
        if (p >= N) continue;
        int gi = b * N + p;
        int bm = b * M + bestm[j];
        float pp = px[j] * px[j] + py[j] * py[j] + pz[j] * pz[j];
        float dist = fmaf(2.0f, bestv[j], pp);      // true squared distance
        g_p2n[gi] = bestm[j];
        int pos = atomicAdd(&g_count[bm], 1);
        if (pos < L_CAP) {
            g_lidx[(size_t)bm * L_CAP + pos] = p;
            g_ldst[(size_t)bm * L_CAP + pos] = dist;
        }
    }
}

// ---------------- k_select: one WARP per (b, m), fused final reduce ---------
#define SEL_THREADS 1024
#define SEL_WARPS (SEL_THREADS / 32)      // 32
#define SEL_BLOCKS (B * M / SEL_WARPS)    // 128  (one wave on 148 SMs)

__global__ __launch_bounds__(SEL_THREADS) void k_select(
        const float* __restrict__ pts,
        const float* __restrict__ kpw,
        const float* __restrict__ pose,
        const float* __restrict__ ow,
        float* __restrict__ out) {
    __shared__ float s_a[SEL_WARPS];
    __shared__ float s_w[SEL_WARPS];

    int wg = (blockIdx.x * SEL_THREADS + threadIdx.x) >> 5;   // global warp id
    int wid = threadIdx.x >> 5;
    int lane = threadIdx.x & 31;
    int b = wg / M;
    int m = wg - b * M;
    int i = wg;

    const float* ptsb = pts + (size_t)b * N * 3;
    const int* lidx = g_lidx + (size_t)i * L_CAP;

    int c = g_count[i];
    if (lane == 0) g_count[i] = 0;     // self-reset for next replay
    int cc = min(c, L_CAP);
    float sx = 0.f, sy = 0.f, sz = 0.f;
    int fill;

    if (c <= PL) {
        for (int j = lane; j < cc; j += 32) {
            int p = lidx[j];
            const float* q = &ptsb[(size_t)p * 3];
            sx += q[0]; sy += q[1]; sz += q[2];
        }
        fill = PL - c;
    } else {
        // Warp-parallel exact top-PL by lex (dist, idx) — matches lax.top_k
        // stability. Keys are unique (idx unique), encoded as u64:
        // high 32 = order-preserving float bits of dist, low 32 = idx.
        const float* ldst = g_ldst + (size_t)i * L_CAP;
        unsigned long long lk[(L_CAP + 31) / 32];   // 6
        int ln = 0;
        for (int j = lane; j < cc; j += 32) {
            float d = ldst[j];
            unsigned u = __float_as_uint(d);
            unsigned enc = (u & 0x80000000u) ? ~u : (u | 0x80000000u);
            unsigned long long key =
                ((unsigned long long)enc << 32) | (unsigned)lidx[j];
            int pos = ln++;
            while (pos > 0 && lk[pos - 1] > key) { lk[pos] = lk[pos - 1]; pos--; }
            lk[pos] = key;
        }
        int pos = 0;
        unsigned long long cand = (pos < ln) ? lk[pos] : ~0ull;
        int mycnt = 0;
        int myidx[2];                    // each lane owns rounds {lane, lane+32}
#pragma unroll 1
        for (int r = 0; r < PL; r++) {
            unsigned hi = (unsigned)(cand >> 32);
            unsigned rhi = __reduce_min_sync(0xffffffffu, hi);
            unsigned lo = (hi == rhi) ? (unsigned)cand : 0xffffffffu;
            unsigned rlo = __reduce_min_sync(0xffffffffu, lo);   // = winning idx
            if (hi == rhi && (unsigned)cand == rlo) {            // unique winner
                pos++;
                cand = (pos < ln) ? lk[pos] : ~0ull;
            }
            if (lane == (r & 31)) myidx[mycnt++] = (int)rlo;
        }
#pragma unroll
        for (int k = 0; k < 2; k++) {
            if (k < mycnt) {
                const float* q = &ptsb[(size_t)myidx[k] * 3];
                sx += q[0]; sy += q[1]; sz += q[2];
            }
        }
        fill = 0;
    }

    // Fillers: first (50 - c) point indices with p2n != m (FAR pad, stable
    // tie-break = ascending index). Warp-cooperative ballot sweep.
    const int* p2nb = g_p2n + (size_t)b * N;
    int n0 = 0;
    while (fill > 0) {
        int n = n0 + lane;                 // n stays far below N (fill <= 50)
        bool ok = (p2nb[n] != m);
        unsigned msk = __ballot_sync(0xffffffffu, ok);
        int rank = __popc(msk & ((1u << lane) - 1u));
        if (ok && rank < fill) {
            const float* q = &ptsb[(size_t)n * 3];
            sx += q[0]; sy += q[1]; sz += q[2];
        }
        fill -= min(fill, __popc(msk));
        n0 += 32;
    }

    // Warp reduce
#pragma unroll
    for (int off = 16; off; off >>= 1) {
        sx += __shfl_xor_sync(0xffffffffu, sx, off);
        sy += __shfl_xor_sync(0xffffffffu, sy, off);
        sz += __shfl_xor_sync(0xffffffffu, sz, off);
    }

    float wa = 0.f, ww = 0.f;
    if (lane == 0) {
        // mean(R p + t) = R mean(p) + t
        const float* P = pose + b * 16;
        float mx = sx * (1.0f / PL), my = sy * (1.0f / PL), mz = sz * (1.0f / PL);
        float ex = P[0] * mx + P[1] * my + P[2]  * mz + P[3]  - kpw[i * 3 + 0];
        float ey = P[4] * mx + P[5] * my + P[6]  * mz + P[7]  - kpw[i * 3 + 1];
        float ez = P[8] * mx + P[9] * my + P[10] * mz + P[11] - kpw[i * 3 + 2];
        float w = ow[i];
        wa = w * (fabsf(ex) + fabsf(ey) + fabsf(ez));
        ww = w;
        s_a[wid] = wa; s_w[wid] = ww;
    }
    __syncthreads();
    if (threadIdx.x == 0) {
        float ba = 0.f, bw = 0.f;
#pragma unroll
        for (int k = 0; k < SEL_WARPS; k++) { ba += s_a[k]; bw += s_w[k]; }
        atomicAdd(&g_accA, (double)ba);
        atomicAdd(&g_accW, (double)bw);
        __threadfence();
        int t = atomicAdd(&g_done, 1);
        if (t == SEL_BLOCKS - 1) {
            double sw = g_accW;
            if (sw < 1e-6) sw = 1e-6;
            out[0] = (float)(g_accA / sw);
            // self-reset for next replay
            g_accA = 0.0;
            g_accW = 0.0;
            g_done = 0;
            __threadfence();
        }
    }
}

extern "C" void kernel_launch(void* const* d_in, const int* in_sizes, int n_in,
                              void* d_out, int out_size) {
    const float* pts  = (const float*)d_in[0];  // (B, N, 3)
    const float* kp   = (const float*)d_in[1];  // (B, M, 3)
    const float* kpw  = (const float*)d_in[2];  // (B, M, 3)
    const float* pose = (const float*)d_in[3];  // (B, 4, 4)
    const float* ow   = (const float*)d_in[4];  // (B, M)
    float* out = (float*)d_out;

    dim3 g1(K1_BLKS, B);
    k_assign<<<g1, K1_THREADS>>>(pts, kp);

    k_select<<<SEL_BLOCKS, SEL_THREADS>>>(pts, kpw, pose, ow, out);
}

// round 6
// speedup vs baseline: 3.4429x; 1.0128x over previous
#include <cuda_runtime.h>
#include <math.h>

#define B 4
#define N 20000
#define M 1024
#define PL 50
#define L_CAP 192   // per-keypoint list capacity (>> max Voronoi occupancy)

// Scratch (allocation-free rule: __device__ globals, zero-initialized at load).
// Pipeline is self-resetting: k_select zeroes g_count / accumulators at the end
// of every launch, so no init kernel is needed.
__device__ int    g_p2n[B * N];
__device__ int    g_count[B * M];
__device__ int    g_lidx[B * M * L_CAP];
__device__ float  g_ldst[B * M * L_CAP];
__device__ double g_accA;
__device__ double g_accW;
__device__ int    g_done;

// ---------------- k_assign: per-point argmin over M keypoints ----------------
// 64-thread blocks, 128 points each -> 157 x 4 = 628 blocks. All resident
// (smem 32KB, 7 blocks/SM cap); max 5 vs avg 4.24 blocks/SM = 1.18 skew
// (vs 1.4 with 316 larger blocks).
#define K1_THREADS 64
#define PPT 2
#define PTS_PER_BLK (K1_THREADS * PPT)   // 128
#define K1_BLKS ((N + PTS_PER_BLK - 1) / PTS_PER_BLK)  // 157

__device__ __forceinline__ unsigned long long pack2(float lo, float hi) {
    unsigned long long d;
    asm("mov.b64 %0, {%1, %2};" : "=l"(d) : "f"(lo), "f"(hi));
    return d;
}

__global__ __launch_bounds__(K1_THREADS) void k_assign(
        const float* __restrict__ pts,
        const float* __restrict__ kp) {
    // Pre-packed f32x2 keypoint layout: skpA[m] = {kx2, ky2}, skpB[m] = {kz2, kw2}
    // where each u64 holds the SAME value duplicated (lo/hi lanes = 2 points).
    __shared__ ulonglong2 skpA[M];
    __shared__ ulonglong2 skpB[M];

    const int b = blockIdx.y;
    const float* kpb = kp + (size_t)b * M * 3;
    for (int m = threadIdx.x; m < M; m += K1_THREADS) {
        float kx = kpb[m * 3 + 0];
        float ky = kpb[m * 3 + 1];
        float kz = kpb[m * 3 + 2];
        float kw = 0.5f * (kx * kx + ky * ky + kz * kz);
        ulonglong2 a, c;
        a.x = pack2(kx, kx); a.y = pack2(ky, ky);
        c.x = pack2(kz, kz); c.y = pack2(kw, kw);
        skpA[m] = a;
        skpB[m] = c;
    }
    __syncthreads();

    const int base = blockIdx.x * PTS_PER_BLK;
    float px[PPT], py[PPT], pz[PPT], bestv[PPT];
    int bestm[PPT];

#pragma unroll
    for (int j = 0; j < PPT; j++) {
        int p = base + j * K1_THREADS + threadIdx.x;
        float x = 0.f, y = 0.f, z = 0.f;
        if (p < N) {
            const float* q = pts + ((size_t)b * N + p) * 3;
            x = q[0]; y = q[1]; z = q[2];
        }
        px[j] = x; py[j] = y; pz[j] = z;
        bestv[j] = INFINITY;
        bestm[j] = 0;
    }

    // packed negated coordinates (lo = point j0, hi = point j1)
    unsigned long long nx2 = pack2(-px[0], -px[1]);
    unsigned long long ny2 = pack2(-py[0], -py[1]);
    unsigned long long nz2 = pack2(-pz[0], -pz[1]);

#pragma unroll 8
    for (int m = 0; m < M; m++) {
        ulonglong2 a = skpA[m];
        ulonglong2 c = skpB[m];
        unsigned long long v2;
        // v = 0.5|k|^2 - k.p  (monotone in true sq-dist for a fixed point)
        asm("fma.rn.f32x2 %0, %1, %2, %3;" : "=l"(v2) : "l"(c.x), "l"(nz2), "l"(c.y));
        asm("fma.rn.f32x2 %0, %1, %2, %3;" : "=l"(v2) : "l"(a.y), "l"(ny2), "l"(v2));
        asm("fma.rn.f32x2 %0, %1, %2, %3;" : "=l"(v2) : "l"(a.x), "l"(nx2), "l"(v2));
        float v0, v1;
        asm("mov.b64 {%0, %1}, %2;" : "=f"(v0), "=f"(v1) : "l"(v2));
        // strict <: first-min like jnp.argmin
        bool lt0 = v0 < bestv[0];
        bestv[0] = lt0 ? v0 : bestv[0];
        bestm[0] = lt0 ? m : bestm[0];
        bool lt1 = v1 < bestv[1];
        bestv[1] = lt1 ? v1 : bestv[1];
        bestm[1] = lt1 ? m : bestm[1];
    }

#pragma unroll
    for (int j = 0; j < PPT; j++) {
        int p = base + j * K1_THREADS + threadIdx.x;
        if (p >= N) continue;
        int gi = b * N + p;
        int bm = b * M + bestm[j];
        float pp = px[j] * px[j] + py[j] * py[j] + pz[j] * pz[j];
        float dist = fmaf(2.0f, bestv[j], pp);      // true squared distance
        g_p2n[gi] = bestm[j];
        int pos = atomicAdd(&g_count[bm], 1);
        if (pos < L_CAP) {
            g_lidx[(size_t)bm * L_CAP + pos] = p;
            g_ldst[(size_t)bm * L_CAP + pos] = dist;
        }
    }
}

// ---------------- k_select: one WARP per (b, m), fused final reduce ---------
// 256-thread blocks: 512 blocks cover all 148 SMs (vs 128 blocks leaving 20
// SMs idle) and shrink the __syncthreads domain from 32 warps to 8.
#define SEL_THREADS 256
#define SEL_WARPS (SEL_THREADS / 32)      // 8
#define SEL_BLOCKS (B * M / SEL_WARPS)    // 512

__global__ __launch_bounds__(SEL_THREADS) void k_select(
        const float* __restrict__ pts,
        const float* __restrict__ kpw,
        const float* __restrict__ pose,
        const float* __restrict__ ow,
        float* __restrict__ out) {
    __shared__ float s_a[SEL_WARPS];
    __shared__ float s_w[SEL_WARPS];

    int wg = (blockIdx.x * SEL_THREADS + threadIdx.x) >> 5;   // global warp id
    int wid = threadIdx.x >> 5;
    int lane = threadIdx.x & 31;
    int b = wg / M;
    int m = wg - b * M;
    int i = wg;

    const float* ptsb = pts + (size_t)b * N * 3;
    const int* lidx = g_lidx + (size_t)i * L_CAP;

    int c = g_count[i];
    if (lane == 0) g_count[i] = 0;     // self-reset for next replay
    int cc = min(c, L_CAP);
    float sx = 0.f, sy = 0.f, sz = 0.f;
    int fill;

    if (c <= PL) {
        for (int j = lane; j < cc; j += 32) {
            int p = lidx[j];
            const float* q = &ptsb[(size_t)p * 3];
            sx += q[0]; sy += q[1]; sz += q[2];
        }
        fill = PL - c;
    } else {
        // Warp-parallel exact top-PL by lex (dist, idx) — matches lax.top_k
        // stability. Keys are unique (idx unique), encoded as u64:
        // high 32 = order-preserving float bits of dist, low 32 = idx.
        const float* ldst = g_ldst + (size_t)i * L_CAP;
        unsigned long long lk[(L_CAP + 31) / 32];   // 6
        int ln = 0;
        for (int j = lane; j < cc; j += 32) {
            float d = ldst[j];
            unsigned u = __float_as_uint(d);
            unsigned enc = (u & 0x80000000u) ? ~u : (u | 0x80000000u);
            unsigned long long key =
                ((unsigned long long)enc << 32) | (unsigned)lidx[j];
            int pos = ln++;
            while (pos > 0 && lk[pos - 1] > key) { lk[pos] = lk[pos - 1]; pos--; }
            lk[pos] = key;
        }
        int pos = 0;
        unsigned long long cand = (pos < ln) ? lk[pos] : ~0ull;
        int mycnt = 0;
        int myidx[2];                    // each lane owns rounds {lane, lane+32}
#pragma unroll 1
        for (int r = 0; r < PL; r++) {
            unsigned hi = (unsigned)(cand >> 32);
            unsigned rhi = __reduce_min_sync(0xffffffffu, hi);
            unsigned lo = (hi == rhi) ? (unsigned)cand : 0xffffffffu;
            unsigned rlo = __reduce_min_sync(0xffffffffu, lo);   // = winning idx
            if (hi == rhi && (unsigned)cand == rlo) {            // unique winner
                pos++;
                cand = (pos < ln) ? lk[pos] : ~0ull;
            }
            if (lane == (r & 31)) myidx[mycnt++] = (int)rlo;
        }
#pragma unroll
        for (int k = 0; k < 2; k++) {
            if (k < mycnt) {
                const float* q = &ptsb[(size_t)myidx[k] * 3];
                sx += q[0]; sy += q[1]; sz += q[2];
            }
        }
        fill = 0;
    }

    // Fillers: first (50 - c) point indices with p2n != m (FAR pad, stable
    // tie-break = ascending index). Warp-cooperative ballot sweep.
    const int* p2nb = g_p2n + (size_t)b * N;
    int n0 = 0;
    while (fill > 0) {
        int n = n0 + lane;                 // n stays far below N (fill <= 50)
        bool ok = (p2nb[n] != m);
        unsigned msk = __ballot_sync(0xffffffffu, ok);
        int rank = __popc(msk & ((1u << lane) - 1u));
        if (ok && rank < fill) {
            const float* q = &ptsb[(size_t)n * 3];
            sx += q[0]; sy += q[1]; sz += q[2];
        }
        fill -= min(fill, __popc(msk));
        n0 += 32;
    }

    // Warp reduce
#pragma unroll
    for (int off = 16; off; off >>= 1) {
        sx += __shfl_xor_sync(0xffffffffu, sx, off);
        sy += __shfl_xor_sync(0xffffffffu, sy, off);
        sz += __shfl_xor_sync(0xffffffffu, sz, off);
    }

    if (lane == 0) {
        // mean(R p + t) = R mean(p) + t
        const float* P = pose + b * 16;
        float mx = sx * (1.0f / PL), my = sy * (1.0f / PL), mz = sz * (1.0f / PL);
        float ex = P[0] * mx + P[1] * my + P[2]  * mz + P[3]  - kpw[i * 3 + 0];
        float ey = P[4] * mx + P[5] * my + P[6]  * mz + P[7]  - kpw[i * 3 + 1];
        float ez = P[8] * mx + P[9] * my + P[10] * mz + P[11] - kpw[i * 3 + 2];
        float w = ow[i];
        s_a[wid] = w * (fabsf(ex) + fabsf(ey) + fabsf(ez));
        s_w[wid] = w;
    }
    __syncthreads();
    if (threadIdx.x == 0) {
        float ba = 0.f, bw = 0.f;
#pragma unroll
        for (int k = 0; k < SEL_WARPS; k++) { ba += s_a[k]; bw += s_w[k]; }
        atomicAdd(&g_accA, (double)ba);
        atomicAdd(&g_accW, (double)bw);
        __threadfence();
        int t = atomicAdd(&g_done, 1);
        if (t == SEL_BLOCKS - 1) {
            double sw = g_accW;
            if (sw < 1e-6) sw = 1e-6;
            out[0] = (float)(g_accA / sw);
            // self-reset for next replay
            g_accA = 0.0;
            g_accW = 0.0;
            g_done = 0;
            __threadfence();
        }
    }
}

extern "C" void kernel_launch(void* const* d_in, const int* in_sizes, int n_in,
                              void* d_out, int out_size) {
    const float* pts  = (const float*)d_in[0];  // (B, N, 3)
    const float* kp   = (const float*)d_in[1];  // (B, M, 3)
    const float* kpw  = (const float*)d_in[2];  // (B, M, 3)
    const float* pose = (const float*)d_in[3];  // (B, 4, 4)
    const float* ow   = (const float*)d_in[4];  // (B, M)
    float* out = (float*)d_out;

    dim3 g1(K1_BLKS, B);
    k_assign<<<g1, K1_THREADS>>>(pts, kp);

    k_select<<<SEL_BLOCKS, SEL_THREADS>>>(pts, kpw, pose, ow, out);
}

// round 7
// speedup vs baseline: 3.7808x; 1.0982x over previous
#include <cuda_runtime.h>
#include <math.h>

#define B 4
#define N 20000
#define M 1024
#define PL 50
#define L_CAP 192   // per-keypoint list capacity (>> max Voronoi occupancy)

// Scratch (allocation-free rule: __device__ globals, zero-initialized at load).
// Pipeline is self-resetting: k_select zeroes g_count / g_done every launch.
__device__ int    g_p2n[B * N];
__device__ int    g_count[B * M];
__device__ int    g_lidx[B * M * L_CAP];
__device__ float  g_ldst[B * M * L_CAP];
__device__ float  g_partA[512];
__device__ float  g_partW[512];
__device__ int    g_done;

__device__ __forceinline__ unsigned long long pack2(float lo, float hi) {
    unsigned long long d;
    asm("mov.b64 %0, {%1, %2};" : "=l"(d) : "f"(lo), "f"(hi));
    return d;
}

// ---------------- k_assign: per-point argmin over M keypoints ----------------
// One point per thread, TWO m's packed per f32x2 op. smem = 16KB (no keypoint
// duplication) -> 1252 blocks of 64 threads, ~8.5 blocks/SM resident,
// ~4.2 warps/SMSP (2x round-6) for latency hiding. Even/odd m's form two
// independent min chains, halving the carried compare-select latency.
#define K1_THREADS 64
#define K1_BLKS ((N + K1_THREADS - 1) / K1_THREADS)   // 313
#define MP (M / 2)                                    // 512 m-pairs

__global__ __launch_bounds__(K1_THREADS) void k_assign(
        const float* __restrict__ pts,
        const float* __restrict__ kp) {
    // sA[mp] = {pack2(kx_e,kx_o), pack2(ky_e,ky_o)}
    // sB[mp] = {pack2(kz_e,kz_o), pack2(kw_e,kw_o)}, kw = 0.5*|k|^2
    __shared__ ulonglong2 sA[MP];
    __shared__ ulonglong2 sB[MP];

    const int b = blockIdx.y;
    const float* kpb = kp + (size_t)b * M * 3;
    for (int mp = threadIdx.x; mp < MP; mp += K1_THREADS) {
        int me = 2 * mp, mo = 2 * mp + 1;
        float ex = kpb[me * 3 + 0], ey = kpb[me * 3 + 1], ez = kpb[me * 3 + 2];
        float ox = kpb[mo * 3 + 0], oy = kpb[mo * 3 + 1], oz = kpb[mo * 3 + 2];
        float ew = 0.5f * (ex * ex + ey * ey + ez * ez);
        float ow_ = 0.5f * (ox * ox + oy * oy + oz * oz);
        ulonglong2 a, c;
        a.x = pack2(ex, ox); a.y = pack2(ey, oy);
        c.x = pack2(ez, oz); c.y = pack2(ew, ow_);
        sA[mp] = a;
        sB[mp] = c;
    }
    __syncthreads();

    const int p = blockIdx.x * K1_THREADS + threadIdx.x;
    float x = 0.f, y = 0.f, z = 0.f;
    if (p < N) {
        const float* q = pts + ((size_t)b * N + p) * 3;
        x = q[0]; y = q[1]; z = q[2];
    }
    unsigned long long nx2 = pack2(-x, -x);
    unsigned long long ny2 = pack2(-y, -y);
    unsigned long long nz2 = pack2(-z, -z);

    float bve = INFINITY, bvo = INFINITY;
    int bme = 0, bmo = 0;       // m-pair indices for even/odd chains

#pragma unroll 8
    for (int mp = 0; mp < MP; mp++) {
        ulonglong2 a = sA[mp];
        ulonglong2 c = sB[mp];
        unsigned long long v2;
        // v = 0.5|k|^2 - k.p  (monotone in true sq-dist for a fixed point)
        asm("fma.rn.f32x2 %0, %1, %2, %3;" : "=l"(v2) : "l"(c.x), "l"(nz2), "l"(c.y));
        asm("fma.rn.f32x2 %0, %1, %2, %3;" : "=l"(v2) : "l"(a.y), "l"(ny2), "l"(v2));
        asm("fma.rn.f32x2 %0, %1, %2, %3;" : "=l"(v2) : "l"(a.x), "l"(nx2), "l"(v2));
        float v0, v1;
        asm("mov.b64 {%0, %1}, %2;" : "=f"(v0), "=f"(v1) : "l"(v2));
        // strict <: keeps FIRST minimum within each chain (ascending m)
        bool le = v0 < bve;
        bve = le ? v0 : bve;
        bme = le ? mp : bme;
        bool lo = v1 < bvo;
        bvo = lo ? v1 : bvo;
        bmo = lo ? mp : bmo;
    }

    if (p < N) {
        // Merge chains. Global first-min: odd wins only if strictly smaller, or
        // equal with smaller m (2*bmo+1 < 2*bme only if bmo < bme).
        int me = 2 * bme, mo = 2 * bmo + 1;
        bool ow2 = (bvo < bve) || (bvo == bve && mo < me);
        float bestv = ow2 ? bvo : bve;
        int bestm = ow2 ? mo : me;

        int gi = b * N + p;
        int bm = b * M + bestm;
        float pp = x * x + y * y + z * z;
        float dist = fmaf(2.0f, bestv, pp);      // true squared distance
        g_p2n[gi] = bestm;
        int pos = atomicAdd(&g_count[bm], 1);
        if (pos < L_CAP) {
            g_lidx[(size_t)bm * L_CAP + pos] = p;
            g_ldst[(size_t)bm * L_CAP + pos] = dist;
        }
    }
}

// ---------------- k_select: one WARP per (b, m), fused final reduce ---------
#define SEL_THREADS 256
#define SEL_WARPS (SEL_THREADS / 32)      // 8
#define SEL_BLOCKS (B * M / SEL_WARPS)    // 512

__global__ __launch_bounds__(SEL_THREADS) void k_select(
        const float* __restrict__ pts,
        const float* __restrict__ kpw,
        const float* __restrict__ pose,
        const float* __restrict__ ow,
        float* __restrict__ out) {
    __shared__ float s_a[SEL_WARPS];
    __shared__ float s_w[SEL_WARPS];
    __shared__ int s_last;

    int wg = (blockIdx.x * SEL_THREADS + threadIdx.x) >> 5;   // global warp id
    int wid = threadIdx.x >> 5;
    int lane = threadIdx.x & 31;
    int b = wg / M;
    int m = wg - b * M;
    int i = wg;

    const float* ptsb = pts + (size_t)b * N * 3;
    const int* lidx = g_lidx + (size_t)i * L_CAP;

    int c = g_count[i];
    if (lane == 0) g_count[i] = 0;     // self-reset for next replay
    int cc = min(c, L_CAP);
    float sx = 0.f, sy = 0.f, sz = 0.f;
    int fill;

    if (c <= PL) {
        for (int j = lane; j < cc; j += 32) {
            int p = lidx[j];
            const float* q = &ptsb[(size_t)p * 3];
            sx += q[0]; sy += q[1]; sz += q[2];
        }
        fill = PL - c;
    } else {
        // Warp-parallel exact top-PL by lex (dist, idx) — matches lax.top_k
        // stability. Keys are unique (idx unique), encoded as u64:
        // high 32 = order-preserving float bits of dist, low 32 = idx.
        const float* ldst = g_ldst + (size_t)i * L_CAP;
        unsigned long long lk[(L_CAP + 31) / 32];   // 6
        int ln = 0;
        for (int j = lane; j < cc; j += 32) {
            float d = ldst[j];
            unsigned u = __float_as_uint(d);
            unsigned enc = (u & 0x80000000u) ? ~u : (u | 0x80000000u);
            unsigned long long key =
                ((unsigned long long)enc << 32) | (unsigned)lidx[j];
            int pos = ln++;
            while (pos > 0 && lk[pos - 1] > key) { lk[pos] = lk[pos - 1]; pos--; }
            lk[pos] = key;
        }
        int pos = 0;
        unsigned long long cand = (pos < ln) ? lk[pos] : ~0ull;
        int mycnt = 0;
        int myidx[2];                    // each lane owns rounds {lane, lane+32}
#pragma unroll 1
        for (int r = 0; r < PL; r++) {
            unsigned hi = (unsigned)(cand >> 32);
            unsigned rhi = __reduce_min_sync(0xffffffffu, hi);
            unsigned lo = (hi == rhi) ? (unsigned)cand : 0xffffffffu;
            unsigned rlo = __reduce_min_sync(0xffffffffu, lo);   // = winning idx
            if (hi == rhi && (unsigned)cand == rlo) {            // unique winner
                pos++;
                cand = (pos < ln) ? lk[pos] : ~0ull;
            }
            if (lane == (r & 31)) myidx[mycnt++] = (int)rlo;
        }
#pragma unroll
        for (int k = 0; k < 2; k++) {
            if (k < mycnt) {
                const float* q = &ptsb[(size_t)myidx[k] * 3];
                sx += q[0]; sy += q[1]; sz += q[2];
            }
        }
        fill = 0;
    }

    // Fillers: first (50 - c) point indices with p2n != m (FAR pad, stable
    // tie-break = ascending index). Warp-cooperative ballot sweep.
    const int* p2nb = g_p2n + (size_t)b * N;
    int n0 = 0;
    while (fill > 0) {
        int n = n0 + lane;                 // n stays far below N (fill <= 50)
        bool ok = (p2nb[n] != m);
        unsigned msk = __ballot_sync(0xffffffffu, ok);
        int rank = __popc(msk & ((1u << lane) - 1u));
        if (ok && rank < fill) {
            const float* q = &ptsb[(size_t)n * 3];
            sx += q[0]; sy += q[1]; sz += q[2];
        }
        fill -= min(fill, __popc(msk));
        n0 += 32;
    }

    // Warp reduce
#pragma unroll
    for (int off = 16; off; off >>= 1) {
        sx += __shfl_xor_sync(0xffffffffu, sx, off);
        sy += __shfl_xor_sync(0xffffffffu, sy, off);
        sz += __shfl_xor_sync(0xffffffffu, sz, off);
    }

    if (lane == 0) {
        // mean(R p + t) = R mean(p) + t
        const float* P = pose + b * 16;
        float mx = sx * (1.0f / PL), my = sy * (1.0f / PL), mz = sz * (1.0f / PL);
        float ex = P[0] * mx + P[1] * my + P[2]  * mz + P[3]  - kpw[i * 3 + 0];
        float ey = P[4] * mx + P[5] * my + P[6]  * mz + P[7]  - kpw[i * 3 + 1];
        float ez = P[8] * mx + P[9] * my + P[10] * mz + P[11] - kpw[i * 3 + 2];
        float w = ow[i];
        s_a[wid] = w * (fabsf(ex) + fabsf(ey) + fabsf(ez));
        s_w[wid] = w;
    }
    __syncthreads();

    // One plain store per block (no contended double atomics), then ticket.
    if (threadIdx.x == 0) {
        float ba = 0.f, bw = 0.f;
#pragma unroll
        for (int k = 0; k < SEL_WARPS; k++) { ba += s_a[k]; bw += s_w[k]; }
        g_partA[blockIdx.x] = ba;
        g_partW[blockIdx.x] = bw;
        __threadfence();
        int t = atomicAdd(&g_done, 1);
        s_last = (t == SEL_BLOCKS - 1);
    }
    __syncthreads();

    if (s_last) {
        __threadfence();
        float a = 0.f, w = 0.f;
        for (int k = threadIdx.x; k < SEL_BLOCKS; k += SEL_THREADS) {
            a += g_partA[k];
            w += g_partW[k];
        }
#pragma unroll
        for (int off = 16; off; off >>= 1) {
            a += __shfl_xor_sync(0xffffffffu, a, off);
            w += __shfl_xor_sync(0xffffffffu, w, off);
        }
        if (lane == 0) { s_a[wid] = a; s_w[wid] = w; }
        __syncthreads();
        if (threadIdx.x == 0) {
            double A = 0.0, W = 0.0;
#pragma unroll
            for (int k = 0; k < SEL_WARPS; k++) { A += s_a[k]; W += s_w[k]; }
            if (W < 1e-6) W = 1e-6;
            out[0] = (float)(A / W);
            g_done = 0;                 // self-reset for next replay
            __threadfence();
        }
    }
}

extern "C" void kernel_launch(void* const* d_in, const int* in_sizes, int n_in,
                              void* d_out, int out_size) {
    const float* pts  = (const float*)d_in[0];  // (B, N, 3)
    const float* kp   = (const float*)d_in[1];  // (B, M, 3)
    const float* kpw  = (const float*)d_in[2];  // (B, M, 3)
    const float* pose = (const float*)d_in[3];  // (B, 4, 4)
    const float* ow   = (const float*)d_in[4];  // (B, M)
    float* out = (float*)d_out;

    dim3 g1(K1_BLKS, B);
    k_assign<<<g1, K1_THREADS>>>(pts, kp);

    k_select<<<SEL_BLOCKS, SEL_THREADS>>>(pts, kpw, pose, ow, out);
}

// round 9
// speedup vs baseline: 3.9468x; 1.0439x over previous
#include <cuda_runtime.h>
#include <math.h>

#define B 4
#define N 20000
#define M 1024
#define PL 50
#define L_CAP 192   // per-keypoint list capacity (>> max Voronoi occupancy)

// Scratch (allocation-free rule: __device__ globals, zero-initialized at load).
// Pipeline is self-resetting: k_select zeroes counters/sums every launch.
__device__ int    g_p2n[B * N];
__device__ int    g_count[B * M];
__device__ float  g_sumx[B * M];
__device__ float  g_sumy[B * M];
__device__ float  g_sumz[B * M];
__device__ int    g_lidx[B * M * L_CAP];
__device__ float  g_ldst[B * M * L_CAP];
__device__ float  g_partA[512];
__device__ float  g_partW[512];
__device__ int    g_done;

__device__ __forceinline__ unsigned long long pack2(float lo, float hi) {
    unsigned long long d;
    asm("mov.b64 %0, {%1, %2};" : "=l"(d) : "f"(lo), "f"(hi));
    return d;
}

// ---------------- k_assign: per-point argmin over M keypoints ----------------
// One point per thread, TWO m's packed per f32x2 op (even/odd min chains).
// Epilogue: per-keypoint coordinate sums via no-return float atomics (RED.ADD)
// so k_select's common path needs no gather at all.
#define K1_THREADS 64
#define K1_BLKS ((N + K1_THREADS - 1) / K1_THREADS)   // 313
#define MP (M / 2)                                    // 512 m-pairs

__global__ __launch_bounds__(K1_THREADS) void k_assign(
        const float* __restrict__ pts,
        const float* __restrict__ kp) {
    // sA[mp] = {pack2(kx_e,kx_o), pack2(ky_e,ky_o)}
    // sB[mp] = {pack2(kz_e,kz_o), pack2(kw_e,kw_o)}, kw = 0.5*|k|^2
    __shared__ ulonglong2 sA[MP];
    __shared__ ulonglong2 sB[MP];

    const int b = blockIdx.y;
    const float* kpb = kp + (size_t)b * M * 3;
    for (int mp = threadIdx.x; mp < MP; mp += K1_THREADS) {
        int me = 2 * mp, mo = 2 * mp + 1;
        float ex = kpb[me * 3 + 0], ey = kpb[me * 3 + 1], ez = kpb[me * 3 + 2];
        float ox = kpb[mo * 3 + 0], oy = kpb[mo * 3 + 1], oz = kpb[mo * 3 + 2];
        float ew = 0.5f * (ex * ex + ey * ey + ez * ez);
        float ow_ = 0.5f * (ox * ox + oy * oy + oz * oz);
        ulonglong2 a, c;
        a.x = pack2(ex, ox); a.y = pack2(ey, oy);
        c.x = pack2(ez, oz); c.y = pack2(ew, ow_);
        sA[mp] = a;
        sB[mp] = c;
    }
    __syncthreads();

    const int p = blockIdx.x * K1_THREADS + threadIdx.x;
    float x = 0.f, y = 0.f, z = 0.f;
    if (p < N) {
        const float* q = pts + ((size_t)b * N + p) * 3;
        x = q[0]; y = q[1]; z = q[2];
    }
    unsigned long long nx2 = pack2(-x, -x);
    unsigned long long ny2 = pack2(-y, -y);
    unsigned long long nz2 = pack2(-z, -z);

    float bve = INFINITY, bvo = INFINITY;
    int bme = 0, bmo = 0;       // m-pair indices for even/odd chains

#pragma unroll 8
    for (int mp = 0; mp < MP; mp++) {
        ulonglong2 a = sA[mp];
        ulonglong2 c = sB[mp];
        unsigned long long v2;
        // v = 0.5|k|^2 - k.p  (monotone in true sq-dist for a fixed point)
        asm("fma.rn.f32x2 %0, %1, %2, %3;" : "=l"(v2) : "l"(c.x), "l"(nz2), "l"(c.y));
        asm("fma.rn.f32x2 %0, %1, %2, %3;" : "=l"(v2) : "l"(a.y), "l"(ny2), "l"(v2));
        asm("fma.rn.f32x2 %0, %1, %2, %3;" : "=l"(v2) : "l"(a.x), "l"(nx2), "l"(v2));
        float v0, v1;
        asm("mov.b64 {%0, %1}, %2;" : "=f"(v0), "=f"(v1) : "l"(v2));
        // strict <: keeps FIRST minimum within each chain (ascending m)
        bool le = v0 < bve;
        bve = le ? v0 : bve;
        bme = le ? mp : bme;
        bool lo = v1 < bvo;
        bvo = lo ? v1 : bvo;
        bmo = lo ? mp : bmo;
    }

    if (p < N) {
        // Merge chains. Global first-min: odd wins only if strictly smaller, or
        // equal with smaller m (2*bmo+1 < 2*bme only if bmo < bme).
        int me = 2 * bme, mo = 2 * bmo + 1;
        bool ow2 = (bvo < bve) || (bvo == bve && mo < me);
        float bestv = ow2 ? bvo : bve;
        int bestm = ow2 ? mo : me;

        int gi = b * N + p;
        int bm = b * M + bestm;
        float pp = x * x + y * y + z * z;
        float dist = fmaf(2.0f, bestv, pp);      // true squared distance
        g_p2n[gi] = bestm;
        // coordinate sums (no-return atomics -> RED.ADD)
        atomicAdd(&g_sumx[bm], x);
        atomicAdd(&g_sumy[bm], y);
        atomicAdd(&g_sumz[bm], z);
        int pos = atomicAdd(&g_count[bm], 1);
        if (pos < L_CAP) {
            g_lidx[(size_t)bm * L_CAP + pos] = p;
            g_ldst[(size_t)bm * L_CAP + pos] = dist;
        }
    }
}

// ---------------- k_select: one WARP per (b, m), fused final reduce ---------
#define SEL_THREADS 256
#define SEL_WARPS (SEL_THREADS / 32)      // 8
#define SEL_BLOCKS (B * M / SEL_WARPS)    // 512

__global__ __launch_bounds__(SEL_THREADS) void k_select(
        const float* __restrict__ pts,
        const float* __restrict__ kpw,
        const float* __restrict__ pose,
        const float* __restrict__ ow,
        float* __restrict__ out) {
    __shared__ float s_a[SEL_WARPS];
    __shared__ float s_w[SEL_WARPS];
    __shared__ int s_last;

    int wg = (blockIdx.x * SEL_THREADS + threadIdx.x) >> 5;   // global warp id
    int wid = threadIdx.x >> 5;
    int lane = threadIdx.x & 31;
    int b = wg / M;
    int m = wg - b * M;
    int i = wg;

    const float* ptsb = pts + (size_t)b * N * 3;
    const int* p2nb = g_p2n + (size_t)b * N;

    // Independent loads up front (all L2-resident from k_assign's writes).
    int c = g_count[i];
    float ssx = g_sumx[i];
    float ssy = g_sumy[i];
    float ssz = g_sumz[i];
    int pv = p2nb[lane];               // prefetch first filler window

    if (lane == 0) {                   // self-reset for next replay
        g_count[i] = 0;
        g_sumx[i] = 0.f; g_sumy[i] = 0.f; g_sumz[i] = 0.f;
    }

    float sx = 0.f, sy = 0.f, sz = 0.f;
    int fill;

    if (c <= PL) {
        // Sum already computed by k_assign's RED.ADD — no gather needed.
        if (lane == 0) { sx = ssx; sy = ssy; sz = ssz; }
        fill = PL - c;
    } else {
        // Warp-parallel exact top-PL by lex (dist, idx) — matches lax.top_k
        // stability. Keys are unique (idx unique), encoded as u64:
        // high 32 = order-preserving float bits of dist, low 32 = idx.
        const int* lidx = g_lidx + (size_t)i * L_CAP;
        const float* ldst = g_ldst + (size_t)i * L_CAP;
        int cc = min(c, L_CAP);
        unsigned long long lk[(L_CAP + 31) / 32];   // 6
        int ln = 0;
        for (int j = lane; j < cc; j += 32) {
            float d = ldst[j];
            unsigned u = __float_as_uint(d);
            unsigned enc = (u & 0x80000000u) ? ~u : (u | 0x80000000u);
            unsigned long long key =
                ((unsigned long long)enc << 32) | (unsigned)lidx[j];
            int pos = ln++;
            while (pos > 0 && lk[pos - 1] > key) { lk[pos] = lk[pos - 1]; pos--; }
            lk[pos] = key;
        }
        int pos = 0;
        unsigned long long cand = (pos < ln) ? lk[pos] : ~0ull;
        int mycnt = 0;
        int myidx[2];                    // each lane owns rounds {lane, lane+32}
#pragma unroll 1
        for (int r = 0; r < PL; r++) {
            unsigned hi = (unsigned)(cand >> 32);
            unsigned rhi = __reduce_min_sync(0xffffffffu, hi);
            unsigned lo = (hi == rhi) ? (unsigned)cand : 0xffffffffu;
            unsigned rlo = __reduce_min_sync(0xffffffffu, lo);   // = winning idx
            if (hi == rhi && (unsigned)cand == rlo) {            // unique winner
                pos++;
                cand = (pos < ln) ? lk[pos] : ~0ull;
            }
            if (lane == (r & 31)) myidx[mycnt++] = (int)rlo;
        }
#pragma unroll
        for (int k = 0; k < 2; k++) {
            if (k < mycnt) {
                const float* q = &ptsb[(size_t)myidx[k] * 3];
                sx += q[0]; sy += q[1]; sz += q[2];
            }
        }
        fill = 0;
    }

    // Fillers: first (50 - c) point indices with p2n != m (FAR pad, stable
    // tie-break = ascending index). Warp-cooperative ballot sweep; p2n values
    // for the first ~130 indices are L1-warm after the first warps touch them.
    int n0 = 0;
    while (fill > 0) {
        int n = n0 + lane;                 // n stays far below N (fill <= 50)
        int pn = (n0 == 0) ? pv : p2nb[n];
        bool ok = (pn != m);
        unsigned msk = __ballot_sync(0xffffffffu, ok);
        int rank = __popc(msk & ((1u << lane) - 1u));
        if (ok && rank < fill) {
            const float* q = &ptsb[(size_t)n * 3];
            sx += q[0]; sy += q[1]; sz += q[2];
        }
        fill -= min(fill, __popc(msk));
        n0 += 32;
    }

    // Warp reduce
#pragma unroll
    for (int off = 16; off; off >>= 1) {
        sx += __shfl_xor_sync(0xffffffffu, sx, off);
        sy += __shfl_xor_sync(0xffffffffu, sy, off);
        sz += __shfl_xor_sync(0xffffffffu, sz, off);
    }

    if (lane == 0) {
        // mean(R p + t) = R mean(p) + t
        const float* P = pose + b * 16;
        float mx = sx * (1.0f / PL), my = sy * (1.0f / PL), mz = sz * (1.0f / PL);
        float ex = P[0] * mx + P[1] * my + P[2]  * mz + P[3]  - kpw[i * 3 + 0];
        float ey = P[4] * mx + P[5] * my + P[6]  * mz + P[7]  - kpw[i * 3 + 1];
        float ez = P[8] * mx + P[9] * my + P[10] * mz + P[11] - kpw[i * 3 + 2];
        float w = ow[i];
        s_a[wid] = w * (fabsf(ex) + fabsf(ey) + fabsf(ez));
        s_w[wid] = w;
    }
    __syncthreads();

    // One plain store per block, then ticket; last block reduces partials.
    if (threadIdx.x == 0) {
        float ba = 0.f, bw = 0.f;
#pragma unroll
        for (int k = 0; k < SEL_WARPS; k++) { ba += s_a[k]; bw += s_w[k]; }
        g_partA[blockIdx.x] = ba;
        g_partW[blockIdx.x] = bw;
        __threadfence();
        int t = atomicAdd(&g_done, 1);
        s_last = (t == SEL_BLOCKS - 1);
    }
    __syncthreads();

    if (s_last) {
        __threadfence();
        float a = 0.f, w = 0.f;
        for (int k = threadIdx.x; k < SEL_BLOCKS; k += SEL_THREADS) {
            a += g_partA[k];
            w += g_partW[k];
        }
#pragma unroll
        for (int off = 16; off; off >>= 1) {
            a += __shfl_xor_sync(0xffffffffu, a, off);
            w += __shfl_xor_sync(0xffffffffu, w, off);
        }
        if (lane == 0) { s_a[wid] = a; s_w[wid] = w; }
        __syncthreads();
        if (threadIdx.x == 0) {
            double A = 0.0, W = 0.0;
#pragma unroll
            for (int k = 0; k < SEL_WARPS; k++) { A += s_a[k]; W += s_w[k]; }
            if (W < 1e-6) W = 1e-6;
            out[0] = (float)(A / W);
            g_done = 0;                 // self-reset for next replay
            __threadfence();
        }
    }
}

extern "C" void kernel_launch(void* const* d_in, const int* in_sizes, int n_in,
                              void* d_out, int out_size) {
    const float* pts  = (const float*)d_in[0];  // (B, N, 3)
    const float* kp   = (const float*)d_in[1];  // (B, M, 3)
    const float* kpw  = (const float*)d_in[2];  // (B, M, 3)
    const float* pose = (const float*)d_in[3];  // (B, 4, 4)
    const float* ow   = (const float*)d_in[4];  // (B, M)
    float* out = (float*)d_out;

    dim3 g1(K1_BLKS, B);
    k_assign<<<g1, K1_THREADS>>>(pts, kp);

    k_select<<<SEL_BLOCKS, SEL_THREADS>>>(pts, kpw, pose, ow, out);
}

// round 10
// speedup vs baseline: 3.9560x; 1.0023x over previous
#include <cuda_runtime.h>
#include <math.h>

#define B 4
#define N 20000
#define M 1024
#define PL 50
#define L_CAP 192   // per-keypoint list capacity (>> max Voronoi occupancy)

// Scratch (allocation-free rule: __device__ globals, zero-initialized at load).
// Pipeline is self-resetting: k_select zeroes counters/sums every launch.
__device__ int    g_p2n[B * N];
__device__ int    g_count[B * M];
__device__ float  g_sumx[B * M];
__device__ float  g_sumy[B * M];
__device__ float  g_sumz[B * M];
__device__ int    g_lidx[B * M * L_CAP];
__device__ float  g_ldst[B * M * L_CAP];
__device__ float  g_partA[512];
__device__ float  g_partW[512];
__device__ int    g_done;

__device__ __forceinline__ unsigned long long pack2(float lo, float hi) {
    unsigned long long d;
    asm("mov.b64 %0, {%1, %2};" : "=l"(d) : "f"(lo), "f"(hi));
    return d;
}

// ---------------- k_assign: per-point argmin over M keypoints ----------------
// One point per thread, TWO m's packed per f32x2 op (even/odd min chains).
// Value-min via fminf (FMNMX -> alu pipe) to offload the saturated fma pipe;
// index select is integer SEL (alu). Epilogue: per-keypoint coordinate sums
// via no-return float atomics (RED.ADD) so k_select needs no gather.
#define K1_THREADS 64
#define K1_BLKS ((N + K1_THREADS - 1) / K1_THREADS)   // 313
#define MP (M / 2)                                    // 512 m-pairs

__global__ __launch_bounds__(K1_THREADS) void k_assign(
        const float* __restrict__ pts,
        const float* __restrict__ kp) {
    // sA[mp] = {pack2(kx_e,kx_o), pack2(ky_e,ky_o)}
    // sB[mp] = {pack2(kz_e,kz_o), pack2(kw_e,kw_o)}, kw = 0.5*|k|^2
    __shared__ ulonglong2 sA[MP];
    __shared__ ulonglong2 sB[MP];

    const int b = blockIdx.y;
    const float* kpb = kp + (size_t)b * M * 3;
    for (int mp = threadIdx.x; mp < MP; mp += K1_THREADS) {
        int me = 2 * mp, mo = 2 * mp + 1;
        float ex = kpb[me * 3 + 0], ey = kpb[me * 3 + 1], ez = kpb[me * 3 + 2];
        float ox = kpb[mo * 3 + 0], oy = kpb[mo * 3 + 1], oz = kpb[mo * 3 + 2];
        float ew = 0.5f * (ex * ex + ey * ey + ez * ez);
        float ow_ = 0.5f * (ox * ox + oy * oy + oz * oz);
        ulonglong2 a, c;
        a.x = pack2(ex, ox); a.y = pack2(ey, oy);
        c.x = pack2(ez, oz); c.y = pack2(ew, ow_);
        sA[mp] = a;
        sB[mp] = c;
    }
    __syncthreads();

    const int p = blockIdx.x * K1_THREADS + threadIdx.x;
    float x = 0.f, y = 0.f, z = 0.f;
    if (p < N) {
        const float* q = pts + ((size_t)b * N + p) * 3;
        x = q[0]; y = q[1]; z = q[2];
    }
    unsigned long long nx2 = pack2(-x, -x);
    unsigned long long ny2 = pack2(-y, -y);
    unsigned long long nz2 = pack2(-z, -z);

    float bve = INFINITY, bvo = INFINITY;
    int bme = 0, bmo = 0;       // m-pair indices for even/odd chains

#pragma unroll 8
    for (int mp = 0; mp < MP; mp++) {
        ulonglong2 a = sA[mp];
        ulonglong2 c = sB[mp];
        unsigned long long v2;
        // v = 0.5|k|^2 - k.p  (monotone in true sq-dist for a fixed point)
        asm("fma.rn.f32x2 %0, %1, %2, %3;" : "=l"(v2) : "l"(c.x), "l"(nz2), "l"(c.y));
        asm("fma.rn.f32x2 %0, %1, %2, %3;" : "=l"(v2) : "l"(a.y), "l"(ny2), "l"(v2));
        asm("fma.rn.f32x2 %0, %1, %2, %3;" : "=l"(v2) : "l"(a.x), "l"(nx2), "l"(v2));
        float v0, v1;
        asm("mov.b64 {%0, %1}, %2;" : "=f"(v0), "=f"(v1) : "l"(v2));
        // strict <: keeps FIRST minimum within each chain (ascending m).
        // fminf -> FMNMX (alu pipe), index -> integer SEL (alu pipe).
        bool le = v0 < bve;
        bme = le ? mp : bme;
        bve = fminf(bve, v0);
        bool lo = v1 < bvo;
        bmo = lo ? mp : bmo;
        bvo = fminf(bvo, v1);
    }

    if (p < N) {
        // Merge chains. Global first-min: odd wins only if strictly smaller, or
        // equal with smaller m (2*bmo+1 < 2*bme only if bmo < bme).
        int me = 2 * bme, mo = 2 * bmo + 1;
        bool ow2 = (bvo < bve) || (bvo == bve && mo < me);
        float bestv = ow2 ? bvo : bve;
        int bestm = ow2 ? mo : me;

        int gi = b * N + p;
        int bm = b * M + bestm;
        float pp = x * x + y * y + z * z;
        float dist = fmaf(2.0f, bestv, pp);      // true squared distance
        g_p2n[gi] = bestm;
        // coordinate sums (no-return atomics -> RED.ADD)
        atomicAdd(&g_sumx[bm], x);
        atomicAdd(&g_sumy[bm], y);
        atomicAdd(&g_sumz[bm], z);
        int pos = atomicAdd(&g_count[bm], 1);
        if (pos < L_CAP) {
            g_lidx[(size_t)bm * L_CAP + pos] = p;
            g_ldst[(size_t)bm * L_CAP + pos] = dist;
        }
    }
}

// ---------------- k_select: one WARP per (b, m), fused final reduce ---------
#define SEL_THREADS 256
#define SEL_WARPS (SEL_THREADS / 32)      // 8
#define SEL_BLOCKS (B * M / SEL_WARPS)    // 512
#define SLOTS (L_CAP / 32)                // 6 keys per lane

__device__ __forceinline__ unsigned long long umax64(unsigned long long a,
                                                     unsigned long long b) {
    return a > b ? a : b;
}

__global__ __launch_bounds__(SEL_THREADS) void k_select(
        const float* __restrict__ pts,
        const float* __restrict__ kpw,
        const float* __restrict__ pose,
        const float* __restrict__ ow,
        float* __restrict__ out) {
    __shared__ float s_a[SEL_WARPS];
    __shared__ float s_w[SEL_WARPS];
    __shared__ int s_last;

    int wg = (blockIdx.x * SEL_THREADS + threadIdx.x) >> 5;   // global warp id
    int wid = threadIdx.x >> 5;
    int lane = threadIdx.x & 31;
    int b = wg / M;
    int m = wg - b * M;
    int i = wg;

    const float* ptsb = pts + (size_t)b * N * 3;
    const int* p2nb = g_p2n + (size_t)b * N;

    // Independent loads up front (all L2-resident from k_assign's writes).
    int c = g_count[i];
    float ssx = g_sumx[i];
    float ssy = g_sumy[i];
    float ssz = g_sumz[i];
    int pv = p2nb[lane];               // prefetch first filler window

    if (lane == 0) {                   // self-reset for next replay
        g_count[i] = 0;
        g_sumx[i] = 0.f; g_sumy[i] = 0.f; g_sumz[i] = 0.f;
    }

    float sx = 0.f, sy = 0.f, sz = 0.f;
    int fill;

    if (c <= PL) {
        // Sum already computed by k_assign's RED.ADD — no gather needed.
        if (lane == 0) { sx = ssx; sy = ssy; sz = ssz; }
        fill = PL - c;
    } else {
        // COMPLEMENT extraction: selected-50 sum = total cell sum minus the
        // (c-50) lex-LARGEST keys (keys unique -> exact complement of the
        // stable top_k smallest). Rounds = c-50 (typically small), not 50.
        // Keys held in statically-indexed registers (no local memory).
        const int* lidx = g_lidx + (size_t)i * L_CAP;
        const float* ldst = g_ldst + (size_t)i * L_CAP;
        int cc = min(c, L_CAP);
        unsigned long long ks[SLOTS];
#pragma unroll
        for (int t = 0; t < SLOTS; t++) {
            int j = lane + 32 * t;
            unsigned long long key = 0ull;          // 0 = empty sentinel
            if (j < cc) {
                float d = ldst[j];
                unsigned u = __float_as_uint(d);
                unsigned enc = (u & 0x80000000u) ? ~u : (u | 0x80000000u);
                key = ((unsigned long long)enc << 32) | (unsigned)lidx[j];
            }
            ks[t] = key;
        }

        if (lane == 0) { sx = ssx; sy = ssy; sz = ssz; }

        int rounds = cc - PL;
#pragma unroll 1
        for (int r = 0; r < rounds; r++) {
            // local max over 6 slots (unrolled tree, static indices)
            unsigned long long lm01 = umax64(ks[0], ks[1]);
            unsigned long long lm23 = umax64(ks[2], ks[3]);
            unsigned long long lm45 = umax64(ks[4], ks[5]);
            unsigned long long lm = umax64(umax64(lm01, lm23), lm45);
            unsigned hi = (unsigned)(lm >> 32);
            unsigned rhi = __reduce_max_sync(0xffffffffu, hi);
            unsigned lo = (hi == rhi) ? (unsigned)lm : 0u;
            unsigned rlo = __reduce_max_sync(0xffffffffu, lo);  // winning idx
            unsigned long long win = ((unsigned long long)rhi << 32) | rlo;
            // remove winner from its owner lane (exactly one match)
#pragma unroll
            for (int t = 0; t < SLOTS; t++)
                if (ks[t] == win) ks[t] = 0ull;
            // subtract winner's coordinates (round-robin owner for MLP)
            if (lane == (r & 31)) {
                const float* q = &ptsb[(size_t)rlo * 3];
                sx -= q[0]; sy -= q[1]; sz -= q[2];
            }
        }
        fill = 0;
    }

    // Fillers: first (50 - c) point indices with p2n != m (FAR pad, stable
    // tie-break = ascending index). Warp-cooperative ballot sweep; p2n values
    // for the first ~130 indices are L1-warm after the first warps touch them.
    int n0 = 0;
    while (fill > 0) {
        int n = n0 + lane;                 // n stays far below N (fill <= 50)
        int pn = (n0 == 0) ? pv : p2nb[n];
        bool ok = (pn != m);
        unsigned msk = __ballot_sync(0xffffffffu, ok);
        int rank = __popc(msk & ((1u << lane) - 1u));
        if (ok && rank < fill) {
            const float* q = &ptsb[(size_t)n * 3];
            sx += q[0]; sy += q[1]; sz += q[2];
        }
        fill -= min(fill, __popc(msk));
        n0 += 32;
    }

    // Warp reduce
#pragma unroll
    for (int off = 16; off; off >>= 1) {
        sx += __shfl_xor_sync(0xffffffffu, sx, off);
        sy += __shfl_xor_sync(0xffffffffu, sy, off);
        sz += __shfl_xor_sync(0xffffffffu, sz, off);
    }

    if (lane == 0) {
        // mean(R p + t) = R mean(p) + t
        const float* P = pose + b * 16;
        float mx = sx * (1.0f / PL), my = sy * (1.0f / PL), mz = sz * (1.0f / PL);
        float ex = P[0] * mx + P[1] * my + P[2]  * mz + P[3]  - kpw[i * 3 + 0];
        float ey = P[4] * mx + P[5] * my + P[6]  * mz + P[7]  - kpw[i * 3 + 1];
        float ez = P[8] * mx + P[9] * my + P[10] * mz + P[11] - kpw[i * 3 + 2];
        float w = ow[i];
        s_a[wid] = w * (fabsf(ex) + fabsf(ey) + fabsf(ez));
        s_w[wid] = w;
    }
    __syncthreads();

    // One plain store per block, then ticket; last block reduces partials.
    if (threadIdx.x == 0) {
        float ba = 0.f, bw = 0.f;
#pragma unroll
        for (int k = 0; k < SEL_WARPS; k++) { ba += s_a[k]; bw += s_w[k]; }
        g_partA[blockIdx.x] = ba;
        g_partW[blockIdx.x] = bw;
        __threadfence();
        int t = atomicAdd(&g_done, 1);
        s_last = (t == SEL_BLOCKS - 1);
    }
    __syncthreads();

    if (s_last) {
        __threadfence();
        float a = 0.f, w = 0.f;
        for (int k = threadIdx.x; k < SEL_BLOCKS; k += SEL_THREADS) {
            a += g_partA[k];
            w += g_partW[k];
        }
#pragma unroll
        for (int off = 16; off; off >>= 1) {
            a += __shfl_xor_sync(0xffffffffu, a, off);
            w += __shfl_xor_sync(0xffffffffu, w, off);
        }
        if (lane == 0) { s_a[wid] = a; s_w[wid] = w; }
        __syncthreads();
        if (threadIdx.x == 0) {
            double A = 0.0, W = 0.0;
#pragma unroll
            for (int k = 0; k < SEL_WARPS; k++) { A += s_a[k]; W += s_w[k]; }
            if (W < 1e-6) W = 1e-6;
            out[0] = (float)(A / W);
            g_done = 0;                 // self-reset for next replay
            __threadfence();
        }
    }
}

extern "C" void kernel_launch(void* const* d_in, const int* in_sizes, int n_in,
                              void* d_out, int out_size) {
    const float* pts  = (const float*)d_in[0];  // (B, N, 3)
    const float* kp   = (const float*)d_in[1];  // (B, M, 3)
    const float* kpw  = (const float*)d_in[2];  // (B, M, 3)
    const float* pose = (const float*)d_in[3];  // (B, 4, 4)
    const float* ow   = (const float*)d_in[4];  // (B, M)
    float* out = (float*)d_out;

    dim3 g1(K1_BLKS, B);
    k_assign<<<g1, K1_THREADS>>>(pts, kp);

    k_select<<<SEL_BLOCKS, SEL_THREADS>>>(pts, kpw, pose, ow, out);
}